// round 1
// baseline (speedup 1.0000x reference)
#include <cuda_runtime.h>

#define NB 2
#define NSEQ 2304
#define NH 8
#define HD 32
#define DIMC 256
#define NTAB 9025
#define CPBH 512
#define MROWS (NB*NSEQ)          // 4608

// -------- device scratch (no allocations allowed) --------
__device__ float g_qkv[MROWS*3*DIMC];       // raw qkv GEMM output [row][768]
__device__ float g_q[NB*NH*NSEQ*HD];        // normalized+scaled q  [bh][n][32]
__device__ float g_k[NB*NH*NSEQ*HD];        // normalized k         [bh][n][32]
__device__ float g_v[NB*NH*NSEQ*HD];        // v                    [bh][n][32]
__device__ float g_att[MROWS*DIMC];         // attention out [b*N+n][256]
__device__ float g_tab[NH*NTAB];            // CPB table, transposed [h][r]
__device__ int   g_idx[NSEQ*NSEQ];          // int32 relative_pos_index
__device__ int   g_is64;

// -------- dtype probe: is relative_pos_index really int64? --------
__global__ void k_flag_init() { g_is64 = 1; }

__global__ void k_flag_scan(const long long* __restrict__ p) {
    // scan first NSEQ*NSEQ/2 int64 slots: safe whichever dtype the buffer is
    long total = (long)NSEQ * NSEQ / 2;
    for (long i = (long)blockIdx.x * blockDim.x + threadIdx.x; i < total;
         i += (long)gridDim.x * blockDim.x) {
        long long v = p[i];
        if (v < 0 || v >= NTAB) g_is64 = 0;
    }
}

__global__ void k_idx_convert(const long long* __restrict__ p) {
    int is64 = g_is64;
    const int* p32 = (const int*)p;
    int total = NSEQ * NSEQ;
    for (int i = blockIdx.x * blockDim.x + threadIdx.x; i < total;
         i += gridDim.x * blockDim.x) {
        g_idx[i] = is64 ? (int)p[i] : p32[i];
    }
}

// -------- CPB MLP: tab[h][r] = (relu(coords @ W1^T + b1) @ W2^T + b2) --------
__global__ void k_cpb(const float* __restrict__ tbl, const float* __restrict__ W1,
                      const float* __restrict__ b1, const float* __restrict__ W2,
                      const float* __restrict__ b2) {
    int w = blockIdx.x * 4 + (threadIdx.x >> 5);
    int lane = threadIdx.x & 31;
    if (w >= NTAB) return;
    float c0 = tbl[2*w], c1 = tbl[2*w+1];
    float a0=0,a1=0,a2=0,a3=0,a4=0,a5=0,a6=0,a7=0;
    for (int j = lane; j < CPBH; j += 32) {
        float hd = fmaxf(fmaf(c0, W1[2*j], fmaf(c1, W1[2*j+1], b1[j])), 0.f);
        a0 = fmaf(hd, W2[0*CPBH+j], a0);
        a1 = fmaf(hd, W2[1*CPBH+j], a1);
        a2 = fmaf(hd, W2[2*CPBH+j], a2);
        a3 = fmaf(hd, W2[3*CPBH+j], a3);
        a4 = fmaf(hd, W2[4*CPBH+j], a4);
        a5 = fmaf(hd, W2[5*CPBH+j], a5);
        a6 = fmaf(hd, W2[6*CPBH+j], a6);
        a7 = fmaf(hd, W2[7*CPBH+j], a7);
    }
    #pragma unroll
    for (int off = 16; off; off >>= 1) {
        a0 += __shfl_xor_sync(0xffffffffu, a0, off);
        a1 += __shfl_xor_sync(0xffffffffu, a1, off);
        a2 += __shfl_xor_sync(0xffffffffu, a2, off);
        a3 += __shfl_xor_sync(0xffffffffu, a3, off);
        a4 += __shfl_xor_sync(0xffffffffu, a4, off);
        a5 += __shfl_xor_sync(0xffffffffu, a5, off);
        a6 += __shfl_xor_sync(0xffffffffu, a6, off);
        a7 += __shfl_xor_sync(0xffffffffu, a7, off);
    }
    if (lane == 0) {
        g_tab[0*NTAB+w] = a0 + b2[0];
        g_tab[1*NTAB+w] = a1 + b2[1];
        g_tab[2*NTAB+w] = a2 + b2[2];
        g_tab[3*NTAB+w] = a3 + b2[3];
        g_tab[4*NTAB+w] = a4 + b2[4];
        g_tab[5*NTAB+w] = a5 + b2[5];
        g_tab[6*NTAB+w] = a6 + b2[6];
        g_tab[7*NTAB+w] = a7 + b2[7];
    }
}

// -------- tiled fp32 GEMM: C[M][N] = A[M][K] @ W[N][K]^T + bias --------
#define BM 128
#define BN 64
#define BK 16
__global__ void __launch_bounds__(256) k_gemm(
        const float* __restrict__ A, const float* __restrict__ W,
        const float* __restrict__ bias, float* __restrict__ C,
        int M, int N, int K) {
    __shared__ __align__(16) float As[BK][BM];
    __shared__ __align__(16) float Bs[BK][BN];
    int tid = threadIdx.x;
    int row0 = blockIdx.y * BM, col0 = blockIdx.x * BN;
    int ty = tid >> 4, tx = tid & 15;          // 16x16 thread grid, 8x4 micro-tile
    float acc[8][4];
    #pragma unroll
    for (int i = 0; i < 8; i++)
        #pragma unroll
        for (int j = 0; j < 4; j++) acc[i][j] = 0.f;

    for (int k0 = 0; k0 < K; k0 += BK) {
        #pragma unroll
        for (int jj = 0; jj < 2; jj++) {
            int f = tid + jj * 256;            // float4 id within 128x16 A tile
            int ar = f >> 2, ac = (f & 3) << 2;
            float4 v = *(const float4*)(A + (size_t)(row0 + ar) * K + k0 + ac);
            As[ac  ][ar] = v.x; As[ac+1][ar] = v.y;
            As[ac+2][ar] = v.z; As[ac+3][ar] = v.w;
        }
        {
            int f = tid;                       // float4 id within 64x16 W tile
            int br = f >> 2, bc = (f & 3) << 2;
            float4 v = *(const float4*)(W + (size_t)(col0 + br) * K + k0 + bc);
            Bs[bc  ][br] = v.x; Bs[bc+1][br] = v.y;
            Bs[bc+2][br] = v.z; Bs[bc+3][br] = v.w;
        }
        __syncthreads();
        #pragma unroll
        for (int kk = 0; kk < BK; kk++) {
            float a[8], bfr[4];
            *(float4*)(a    ) = *(const float4*)&As[kk][ty*8];
            *(float4*)(a + 4) = *(const float4*)&As[kk][ty*8 + 4];
            *(float4*)(bfr  ) = *(const float4*)&Bs[kk][tx*4];
            #pragma unroll
            for (int i = 0; i < 8; i++)
                #pragma unroll
                for (int j = 0; j < 4; j++)
                    acc[i][j] = fmaf(a[i], bfr[j], acc[i][j]);
        }
        __syncthreads();
    }
    float4 bb = *(const float4*)(bias + col0 + tx*4);
    #pragma unroll
    for (int i = 0; i < 8; i++) {
        float4 o;
        o.x = acc[i][0] + bb.x; o.y = acc[i][1] + bb.y;
        o.z = acc[i][2] + bb.z; o.w = acc[i][3] + bb.w;
        *(float4*)(C + (size_t)(row0 + ty*8 + i) * N + col0 + tx*4) = o;
    }
}

// -------- split qkv, l2-normalize q/k, apply embedding + softplus scale --------
__global__ void k_qkvpost(const float* __restrict__ temp, const float* __restrict__ seq,
                          const float* __restrict__ emb) {
    int gid = blockIdx.x * 4 + (threadIdx.x >> 5);   // gid = bh*NSEQ + n
    int lane = threadIdx.x & 31;
    int n  = gid % NSEQ;
    int bh = gid / NSEQ;
    int h = bh & 7, b = bh >> 3;
    const float* rp = g_qkv + (size_t)(b * NSEQ + n) * (3 * DIMC);
    float qv = rp[            h * HD + lane];
    float kv = rp[DIMC      + h * HD + lane];
    float vv = rp[2 * DIMC  + h * HD + lane];
    float sq = qv * qv, sk = kv * kv;
    #pragma unroll
    for (int off = 16; off; off >>= 1) {
        sq += __shfl_xor_sync(0xffffffffu, sq, off);
        sk += __shfl_xor_sync(0xffffffffu, sk, off);
    }
    sq = sqrtf(sq); sk = sqrtf(sk);
    float scale = log1pf(expf(temp[h])) * seq[0];
    float qn = (qv / fmaxf(sq, 1e-12f) + emb[h * HD + lane]) * scale;
    float kn =  kv / fmaxf(sk, 1e-12f);
    size_t o = (size_t)gid * HD + lane;
    g_q[o] = qn; g_k[o] = kn; g_v[o] = vv;
}

// -------- flash attention: 1 thread = 1 query row, online softmax, bias from SMEM --------
#define MTILE 32
__global__ void __launch_bounds__(128) k_flash() {
    __shared__ float tab_s[9056];                     // per-head bias table column
    __shared__ __align__(16) float Ks[MTILE * HD];
    __shared__ __align__(16) float Vs[MTILE * HD];
    int tid = threadIdx.x;
    int bh = blockIdx.x;
    int h = bh & 7, b = bh >> 3;
    int n = blockIdx.y * 128 + tid;

    for (int i = tid; i < NTAB; i += 128) tab_s[i] = g_tab[h * NTAB + i];

    float4 q[8];
    const float4* qp = (const float4*)(g_q + ((size_t)bh * NSEQ + n) * HD);
    #pragma unroll
    for (int i = 0; i < 8; i++) q[i] = qp[i];

    float4 acc[8];
    #pragma unroll
    for (int i = 0; i < 8; i++) acc[i] = make_float4(0.f, 0.f, 0.f, 0.f);
    float l = 0.f, mx = -1e30f;

    const int*   idxrow = g_idx + (size_t)n * NSEQ;
    const float* kb = g_k + (size_t)bh * NSEQ * HD;
    const float* vb = g_v + (size_t)bh * NSEQ * HD;

    for (int m0 = 0; m0 < NSEQ; m0 += MTILE) {
        __syncthreads();                               // covers tab_s on iter 0
        #pragma unroll
        for (int j = 0; j < 2; j++) {
            int f = tid + j * 128;                     // float4 id, 256 total
            ((float4*)Ks)[f] = *(const float4*)(kb + (size_t)m0 * HD + f * 4);
            ((float4*)Vs)[f] = *(const float4*)(vb + (size_t)m0 * HD + f * 4);
        }
        __syncthreads();
        #pragma unroll 2
        for (int m = 0; m < MTILE; m++) {
            float bias = tab_s[idxrow[m0 + m]];
            const float4* kr = (const float4*)(Ks + m * HD);
            float s0 = bias, s1 = 0.f, s2 = 0.f, s3 = 0.f;
            #pragma unroll
            for (int i = 0; i < 8; i++) {
                float4 kv = kr[i];
                s0 = fmaf(q[i].x, kv.x, s0);
                s1 = fmaf(q[i].y, kv.y, s1);
                s2 = fmaf(q[i].z, kv.z, s2);
                s3 = fmaf(q[i].w, kv.w, s3);
            }
            float s = (s0 + s1) + (s2 + s3);
            if (__any_sync(0xffffffffu, s > mx)) {     // rare after warmup
                float nm = fmaxf(mx, s);
                float c = __expf(mx - nm);
                l *= c;
                #pragma unroll
                for (int i = 0; i < 8; i++) {
                    acc[i].x *= c; acc[i].y *= c; acc[i].z *= c; acc[i].w *= c;
                }
                mx = nm;
            }
            float p = __expf(s - mx);
            l += p;
            const float4* vr = (const float4*)(Vs + m * HD);
            #pragma unroll
            for (int i = 0; i < 8; i++) {
                float4 vv = vr[i];
                acc[i].x = fmaf(p, vv.x, acc[i].x);
                acc[i].y = fmaf(p, vv.y, acc[i].y);
                acc[i].z = fmaf(p, vv.z, acc[i].z);
                acc[i].w = fmaf(p, vv.w, acc[i].w);
            }
        }
    }
    float inv = 1.f / l;
    float4* op = (float4*)(g_att + (size_t)(b * NSEQ + n) * DIMC + h * HD);
    #pragma unroll
    for (int i = 0; i < 8; i++) {
        float4 o;
        o.x = acc[i].x * inv; o.y = acc[i].y * inv;
        o.z = acc[i].z * inv; o.w = acc[i].w * inv;
        op[i] = o;
    }
}

extern "C" void kernel_launch(void* const* d_in, const int* in_sizes, int n_in,
                              void* d_out, int out_size) {
    const float*     x     = (const float*)d_in[0];
    const long long* rpi   = (const long long*)d_in[1];
    const float*     rct   = (const float*)d_in[2];
    const float*     seq   = (const float*)d_in[3];
    // d_in[4] padding_mask: unused by reference math
    const float*     Wqkv  = (const float*)d_in[5];
    const float*     bqkv  = (const float*)d_in[6];
    const float*     temp  = (const float*)d_in[7];
    const float*     emb   = (const float*)d_in[8];
    const float*     Wproj = (const float*)d_in[9];
    const float*     bproj = (const float*)d_in[10];
    const float*     W1    = (const float*)d_in[11];
    const float*     b1    = (const float*)d_in[12];
    const float*     W2    = (const float*)d_in[13];
    const float*     b2    = (const float*)d_in[14];
    float* out = (float*)d_out;

    float *p_qkv, *p_att;
    cudaGetSymbolAddress((void**)&p_qkv, g_qkv);
    cudaGetSymbolAddress((void**)&p_att, g_att);

    k_flag_init<<<1, 1>>>();
    k_flag_scan<<<512, 256>>>(rpi);
    k_idx_convert<<<2048, 256>>>(rpi);
    k_cpb<<<(NTAB + 3) / 4, 128>>>(rct, W1, b1, W2, b2);
    k_gemm<<<dim3(3 * DIMC / BN, MROWS / BM), 256>>>(x, Wqkv, bqkv, p_qkv,
                                                     MROWS, 3 * DIMC, DIMC);
    k_qkvpost<<<(NB * NH * NSEQ) / 4, 128>>>(temp, seq, emb);
    k_flash<<<dim3(NB * NH, NSEQ / 128), 128>>>();
    k_gemm<<<dim3(DIMC / BN, MROWS / BM), 256>>>(p_att, Wproj, bproj, out,
                                                 MROWS, DIMC, DIMC);
}

// round 2
// speedup vs baseline: 1.2488x; 1.2488x over previous
#include <cuda_runtime.h>

#define NB 2
#define NSEQ 2304
#define NH 8
#define HD 32
#define DIMC 256
#define NTAB 9025
#define CPBH 512
#define MROWS (NB*NSEQ)          // 4608

typedef unsigned long long u64;

// ---- packed f32x2 helpers (Blackwell FFMA2 — PTX only) ----
__device__ __forceinline__ u64 pk(float lo, float hi) {
    u64 r; asm("mov.b64 %0,{%1,%2};" : "=l"(r) : "f"(lo), "f"(hi)); return r;
}
__device__ __forceinline__ void upk(u64 v, float& lo, float& hi) {
    asm("mov.b64 {%0,%1},%2;" : "=f"(lo), "=f"(hi) : "l"(v));
}
__device__ __forceinline__ u64 f2fma(u64 a, u64 b, u64 c) {
    u64 r; asm("fma.rn.f32x2 %0,%1,%2,%3;" : "=l"(r) : "l"(a), "l"(b), "l"(c)); return r;
}
__device__ __forceinline__ u64 f2mul(u64 a, u64 b) {
    u64 r; asm("mul.rn.f32x2 %0,%1,%2;" : "=l"(r) : "l"(a), "l"(b)); return r;
}
__device__ __forceinline__ u64 f2add(u64 a, u64 b) {
    u64 r; asm("add.rn.f32x2 %0,%1,%2;" : "=l"(r) : "l"(a), "l"(b)); return r;
}

// -------- device scratch --------
__device__ float g_qkv[MROWS*3*DIMC];
__device__ float g_q[NB*NH*NSEQ*HD];
__device__ float g_k[NB*NH*NSEQ*HD];
__device__ float g_v[NB*NH*NSEQ*HD];
__device__ float g_att[MROWS*DIMC];
__device__ float g_tab[NH*NTAB];
__device__ int   g_idxT[NSEQ*NSEQ];         // TRANSPOSED: [m][n]
__device__ int   g_is64;

// -------- dtype probe --------
__global__ void k_flag_init() { g_is64 = 1; }

__global__ void k_flag_scan(const long long* __restrict__ p) {
    long total = (long)NSEQ * NSEQ / 2;
    for (long i = (long)blockIdx.x * blockDim.x + threadIdx.x; i < total;
         i += (long)gridDim.x * blockDim.x) {
        long long v = p[i];
        if (v < 0 || v >= NTAB) g_is64 = 0;
    }
}

// -------- convert int64->int32 AND transpose (tiled) --------
__global__ void k_idx_convert(const long long* __restrict__ p) {
    __shared__ int t[32][33];
    int is64 = g_is64;
    const int* p32 = (const int*)p;
    int bx = blockIdx.x * 32, by = blockIdx.y * 32;
    #pragma unroll
    for (int j = 0; j < 32; j += 8) {
        long src = (long)(by + threadIdx.y + j) * NSEQ + bx + threadIdx.x;
        t[threadIdx.y + j][threadIdx.x] = is64 ? (int)p[src] : p32[src];
    }
    __syncthreads();
    #pragma unroll
    for (int j = 0; j < 32; j += 8) {
        long dst = (long)(bx + threadIdx.y + j) * NSEQ + by + threadIdx.x;
        g_idxT[dst] = t[threadIdx.x][threadIdx.y + j];
    }
}

// -------- CPB MLP --------
__global__ void k_cpb(const float* __restrict__ tbl, const float* __restrict__ W1,
                      const float* __restrict__ b1, const float* __restrict__ W2,
                      const float* __restrict__ b2) {
    int w = blockIdx.x * 4 + (threadIdx.x >> 5);
    int lane = threadIdx.x & 31;
    if (w >= NTAB) return;
    float c0 = tbl[2*w], c1 = tbl[2*w+1];
    u64 a01 = 0, a23 = 0, a45 = 0, a67 = 0;
    for (int j = lane; j < CPBH; j += 32) {
        float hd = fmaxf(fmaf(c0, W1[2*j], fmaf(c1, W1[2*j+1], b1[j])), 0.f);
        u64 hh = pk(hd, hd);
        a01 = f2fma(hh, pk(W2[0*CPBH+j], W2[1*CPBH+j]), a01);
        a23 = f2fma(hh, pk(W2[2*CPBH+j], W2[3*CPBH+j]), a23);
        a45 = f2fma(hh, pk(W2[4*CPBH+j], W2[5*CPBH+j]), a45);
        a67 = f2fma(hh, pk(W2[6*CPBH+j], W2[7*CPBH+j]), a67);
    }
    float a[8];
    upk(a01, a[0], a[1]); upk(a23, a[2], a[3]);
    upk(a45, a[4], a[5]); upk(a67, a[6], a[7]);
    #pragma unroll
    for (int i = 0; i < 8; i++)
        #pragma unroll
        for (int off = 16; off; off >>= 1)
            a[i] += __shfl_xor_sync(0xffffffffu, a[i], off);
    if (lane == 0) {
        #pragma unroll
        for (int i = 0; i < 8; i++) g_tab[i*NTAB + w] = a[i] + b2[i];
    }
}

// -------- tiled fp32 GEMM with packed FFMA2: C = A @ W^T + bias --------
#define BM 128
#define BN 64
#define BK 16
__global__ void __launch_bounds__(256) k_gemm(
        const float* __restrict__ A, const float* __restrict__ W,
        const float* __restrict__ bias, float* __restrict__ C,
        int M, int N, int K) {
    __shared__ __align__(16) float As[BK][BM];
    __shared__ __align__(16) float Bs[BK][BN];
    int tid = threadIdx.x;
    int row0 = blockIdx.y * BM, col0 = blockIdx.x * BN;
    int ty = tid >> 4, tx = tid & 15;
    u64 acc2[4][4];                          // packed over M (rows 2i,2i+1) x cols j
    #pragma unroll
    for (int i = 0; i < 4; i++)
        #pragma unroll
        for (int j = 0; j < 4; j++) acc2[i][j] = 0ull;

    for (int k0 = 0; k0 < K; k0 += BK) {
        #pragma unroll
        for (int jj = 0; jj < 2; jj++) {
            int f = tid + jj * 256;
            int ar = f >> 2, ac = (f & 3) << 2;
            float4 v = *(const float4*)(A + (size_t)(row0 + ar) * K + k0 + ac);
            As[ac  ][ar] = v.x; As[ac+1][ar] = v.y;
            As[ac+2][ar] = v.z; As[ac+3][ar] = v.w;
        }
        {
            int f = tid;
            int br = f >> 2, bc = (f & 3) << 2;
            float4 v = *(const float4*)(W + (size_t)(col0 + br) * K + k0 + bc);
            Bs[bc  ][br] = v.x; Bs[bc+1][br] = v.y;
            Bs[bc+2][br] = v.z; Bs[bc+3][br] = v.w;
        }
        __syncthreads();
        #pragma unroll
        for (int kk = 0; kk < BK; kk++) {
            ulonglong2 aA = *(const ulonglong2*)&As[kk][ty*8];
            ulonglong2 aB = *(const ulonglong2*)&As[kk][ty*8 + 4];
            u64 a2[4] = {aA.x, aA.y, aB.x, aB.y};
            float4 bq = *(const float4*)&Bs[kk][tx*4];
            u64 bd[4] = {pk(bq.x,bq.x), pk(bq.y,bq.y), pk(bq.z,bq.z), pk(bq.w,bq.w)};
            #pragma unroll
            for (int i = 0; i < 4; i++)
                #pragma unroll
                for (int j = 0; j < 4; j++)
                    acc2[i][j] = f2fma(a2[i], bd[j], acc2[i][j]);
        }
        __syncthreads();
    }
    float4 bb = *(const float4*)(bias + col0 + tx*4);
    #pragma unroll
    for (int i = 0; i < 4; i++) {
        float lo[4], hi[4];
        #pragma unroll
        for (int j = 0; j < 4; j++) upk(acc2[i][j], lo[j], hi[j]);
        float4 o0, o1;
        o0.x = lo[0]+bb.x; o0.y = lo[1]+bb.y; o0.z = lo[2]+bb.z; o0.w = lo[3]+bb.w;
        o1.x = hi[0]+bb.x; o1.y = hi[1]+bb.y; o1.z = hi[2]+bb.z; o1.w = hi[3]+bb.w;
        *(float4*)(C + (size_t)(row0 + ty*8 + 2*i    ) * N + col0 + tx*4) = o0;
        *(float4*)(C + (size_t)(row0 + ty*8 + 2*i + 1) * N + col0 + tx*4) = o1;
    }
}

// -------- qkv postprocess --------
__global__ void k_qkvpost(const float* __restrict__ temp, const float* __restrict__ seq,
                          const float* __restrict__ emb) {
    int gid = blockIdx.x * 4 + (threadIdx.x >> 5);
    int lane = threadIdx.x & 31;
    int n  = gid % NSEQ;
    int bh = gid / NSEQ;
    int h = bh & 7, b = bh >> 3;
    const float* rp = g_qkv + (size_t)(b * NSEQ + n) * (3 * DIMC);
    float qv = rp[            h * HD + lane];
    float kv = rp[DIMC      + h * HD + lane];
    float vv = rp[2 * DIMC  + h * HD + lane];
    float sq = qv * qv, sk = kv * kv;
    #pragma unroll
    for (int off = 16; off; off >>= 1) {
        sq += __shfl_xor_sync(0xffffffffu, sq, off);
        sk += __shfl_xor_sync(0xffffffffu, sk, off);
    }
    sq = sqrtf(sq); sk = sqrtf(sk);
    float scale = log1pf(expf(temp[h])) * seq[0];
    float qn = (qv / fmaxf(sq, 1e-12f) + emb[h * HD + lane]) * scale;
    float kn =  kv / fmaxf(sk, 1e-12f);
    size_t o = (size_t)gid * HD + lane;
    g_q[o] = qn; g_k[o] = kn; g_v[o] = vv;
}

// -------- flash attention, packed f32x2, 256 rows per CTA, 1 wave --------
#define FT 256
#define MTILE 32
#define TAB_PAD 9056
__global__ void __launch_bounds__(FT) k_flash() {
    extern __shared__ __align__(16) float dsm[];
    float* tab_s = dsm;                               // 9056 floats
    float* Ks    = dsm + TAB_PAD;                     // 1024 floats
    float* Vs    = dsm + TAB_PAD + 1024;              // 1024 floats
    int*   idx_s = (int*)(dsm + TAB_PAD + 2048);      // 32*256 ints

    int tid = threadIdx.x;
    int bh = blockIdx.x;
    int h = bh & 7, b = bh >> 3;
    int n0 = blockIdx.y * FT;
    int n = n0 + tid;

    for (int i = tid; i < NTAB; i += FT) tab_s[i] = g_tab[h * NTAB + i];

    u64 q2[16];
    const ulonglong2* qp = (const ulonglong2*)(g_q + ((size_t)bh * NSEQ + n) * HD);
    #pragma unroll
    for (int i = 0; i < 8; i++) { ulonglong2 t = qp[i]; q2[2*i] = t.x; q2[2*i+1] = t.y; }

    u64 acc2[16];
    #pragma unroll
    for (int i = 0; i < 16; i++) acc2[i] = 0ull;
    float l = 0.f, mx = -1e30f;

    const float* kb = g_k + (size_t)bh * NSEQ * HD;
    const float* vb = g_v + (size_t)bh * NSEQ * HD;

    for (int m0 = 0; m0 < NSEQ; m0 += MTILE) {
        __syncthreads();                               // covers tab_s on iter 0
        ((float4*)Ks)[tid] = *(const float4*)(kb + (size_t)m0 * HD + tid * 4);
        ((float4*)Vs)[tid] = *(const float4*)(vb + (size_t)m0 * HD + tid * 4);
        #pragma unroll
        for (int m = 0; m < MTILE; m++)
            idx_s[m * FT + tid] = g_idxT[(size_t)(m0 + m) * NSEQ + n];
        __syncthreads();
        #pragma unroll 2
        for (int m = 0; m < MTILE; m++) {
            float bias = tab_s[idx_s[m * FT + tid]];
            const ulonglong2* kr = (const ulonglong2*)(Ks + m * HD);
            u64 s0 = pk(bias, 0.f), s1 = 0ull, s2 = 0ull, s3 = 0ull;
            #pragma unroll
            for (int i = 0; i < 4; i++) {
                ulonglong2 ka = kr[2*i], kbb = kr[2*i+1];
                s0 = f2fma(q2[4*i  ], ka.x,  s0);
                s1 = f2fma(q2[4*i+1], ka.y,  s1);
                s2 = f2fma(q2[4*i+2], kbb.x, s2);
                s3 = f2fma(q2[4*i+3], kbb.y, s3);
            }
            u64 st = f2add(f2add(s0, s1), f2add(s2, s3));
            float slo, shi; upk(st, slo, shi);
            float s = slo + shi;
            if (__any_sync(0xffffffffu, s > mx)) {
                float nm = fmaxf(mx, s);
                float c = __expf(mx - nm);
                l *= c;
                u64 cc = pk(c, c);
                #pragma unroll
                for (int i = 0; i < 16; i++) acc2[i] = f2mul(acc2[i], cc);
                mx = nm;
            }
            float p = __expf(s - mx);
            l += p;
            u64 pp = pk(p, p);
            const ulonglong2* vr = (const ulonglong2*)(Vs + m * HD);
            #pragma unroll
            for (int i = 0; i < 8; i++) {
                ulonglong2 vv = vr[i];
                acc2[2*i  ] = f2fma(pp, vv.x, acc2[2*i  ]);
                acc2[2*i+1] = f2fma(pp, vv.y, acc2[2*i+1]);
            }
        }
    }
    float inv = 1.f / l;
    float* op = g_att + (size_t)(b * NSEQ + n) * DIMC + h * HD;
    #pragma unroll
    for (int i = 0; i < 8; i++) {
        float x0, x1, x2, x3;
        upk(acc2[2*i], x0, x1); upk(acc2[2*i+1], x2, x3);
        float4 o; o.x = x0*inv; o.y = x1*inv; o.z = x2*inv; o.w = x3*inv;
        *(float4*)(op + 4*i) = o;
    }
}

#define FLASH_SMEM ((TAB_PAD + 2048) * 4 + MTILE * FT * 4)

extern "C" void kernel_launch(void* const* d_in, const int* in_sizes, int n_in,
                              void* d_out, int out_size) {
    const float*     x     = (const float*)d_in[0];
    const long long* rpi   = (const long long*)d_in[1];
    const float*     rct   = (const float*)d_in[2];
    const float*     seq   = (const float*)d_in[3];
    const float*     Wqkv  = (const float*)d_in[5];
    const float*     bqkv  = (const float*)d_in[6];
    const float*     temp  = (const float*)d_in[7];
    const float*     emb   = (const float*)d_in[8];
    const float*     Wproj = (const float*)d_in[9];
    const float*     bproj = (const float*)d_in[10];
    const float*     W1    = (const float*)d_in[11];
    const float*     b1    = (const float*)d_in[12];
    const float*     W2    = (const float*)d_in[13];
    const float*     b2    = (const float*)d_in[14];
    float* out = (float*)d_out;

    float *p_qkv, *p_att;
    cudaGetSymbolAddress((void**)&p_qkv, g_qkv);
    cudaGetSymbolAddress((void**)&p_att, g_att);

    static int smem_set = 0;
    if (!smem_set) {
        cudaFuncSetAttribute(k_flash, cudaFuncAttributeMaxDynamicSharedMemorySize,
                             FLASH_SMEM);
        smem_set = 1;
    }

    k_flag_init<<<1, 1>>>();
    k_flag_scan<<<512, 256>>>(rpi);
    k_idx_convert<<<dim3(NSEQ/32, NSEQ/32), dim3(32, 8)>>>(rpi);
    k_cpb<<<(NTAB + 3) / 4, 128>>>(rct, W1, b1, W2, b2);
    k_gemm<<<dim3(3 * DIMC / BN, MROWS / BM), 256>>>(x, Wqkv, bqkv, p_qkv,
                                                     MROWS, 3 * DIMC, DIMC);
    k_qkvpost<<<(NB * NH * NSEQ) / 4, 128>>>(temp, seq, emb);
    k_flash<<<dim3(NB * NH, NSEQ / FT), FT, FLASH_SMEM>>>();
    k_gemm<<<dim3(DIMC / BN, MROWS / BM), 256>>>(p_att, Wproj, bproj, out,
                                                 MROWS, DIMC, DIMC);
}